// round 16
// baseline (speedup 1.0000x reference)
#include <cuda_runtime.h>

// Sorted segment-sum: pred_rgb[r] = sum over samples s of ray r of w_s * rgb_s
// CONVERGED FINAL (5 reproductions: 29.15/29.4/29.47/30.1/30.4us; kernel
// 27.5-29.2us at 6.0-6.3TB/s = B300 path-independent LTS cap ~6300 B/cyc).
// Controlled experiments falsified all structural alternatives:
//   R5 smem-staged rgb (L1 pipe contention), R6 256-sample tiles (occ loss),
//   R8 persistent (reg bloat 46), R9/R10 persistent iso-occupancy (grid-
//   stride loop serializes load batches vs 65K independent warps),
//   R14 block 512 (neutral, worse occ quantization).
// Configuration:
//  - flat launch, warp tile = 128 samples, lane chunk = 4: seg int4 +
//    w float4 coalesced, rgb 3x float4 at 48B lane stride, all __ldcs
//    (169MB read-once > 126MB L2, evict-first).
//  - per-lane register accumulation; rare internal segment boundary flushes
//    directly with atomicAdd (RED, no return).
//  - warp segmented suffix reduction over tail partials (sorted keys => runs
//    are lane-contiguous; 5 shfl.down steps); only run-head lanes emit the
//    3 atomics (~9 RED / 128 samples => ~600K total vs 25M naive).
//  - cudaMemsetAsync graph memset node zeroes the poisoned output; same-
//    stream ordering completes it before any atomics (semantically required).

__global__ void __launch_bounds__(256) integrate_kernel(
    const int*   __restrict__ seg,
    const float* __restrict__ rgb,
    const float* __restrict__ w,
    float*       __restrict__ out,
    int n)
{
    const int lane = threadIdx.x & 31;
    const long long warp_global =
        ((long long)blockIdx.x * blockDim.x + threadIdx.x) >> 5;
    const long long tileBase = warp_global * 128;
    if (tileBase >= n) return;            // warp-uniform exit only

    const long long base = tileBase + 4LL * lane;
    const bool valid = base < n;

    int   key;
    float ar = 0.0f, ag = 0.0f, ab = 0.0f;

    if (valid && base + 4 <= n) {
        // Front-batched streaming loads (evict-first).
        const int4   s4 = __ldcs(reinterpret_cast<const int4*>(seg + base));
        const float4 w4 = __ldcs(reinterpret_cast<const float4*>(w + base));
        const float4* r4 = reinterpret_cast<const float4*>(rgb + base * 3);
        const float4 ra = __ldcs(r4 + 0);
        const float4 rb = __ldcs(r4 + 1);
        const float4 rc = __ldcs(r4 + 2);

        // AoS float3 layout within the 3 float4s:
        //   s0: ra.x ra.y ra.z | s1: ra.w rb.x rb.y
        //   s2: rb.z rb.w rc.x | s3: rc.y rc.z rc.w
        const int   s[4] = {s4.x, s4.y, s4.z, s4.w};
        const float W[4] = {w4.x, w4.y, w4.z, w4.w};
        const float R[4] = {ra.x, ra.w, rb.z, rc.y};
        const float G[4] = {ra.y, rb.x, rb.w, rc.z};
        const float B[4] = {ra.z, rb.y, rc.x, rc.w};

        key = s[0];
#pragma unroll
        for (int i = 0; i < 4; i++) {
            if (s[i] != key) {                 // rare internal boundary
                atomicAdd(out + 3 * key + 0, ar);
                atomicAdd(out + 3 * key + 1, ag);
                atomicAdd(out + 3 * key + 2, ab);
                key = s[i];
                ar = ag = ab = 0.0f;
            }
            ar = fmaf(W[i], R[i], ar);
            ag = fmaf(W[i], G[i], ag);
            ab = fmaf(W[i], B[i], ab);
        }
    } else if (valid) {
        // Scalar tail path.
        key = seg[base];
        for (int i = 0; i < 4 && base + i < n; i++) {
            const int si = seg[base + i];
            if (si != key) {
                atomicAdd(out + 3 * key + 0, ar);
                atomicAdd(out + 3 * key + 1, ag);
                atomicAdd(out + 3 * key + 2, ab);
                key = si;
                ar = ag = ab = 0.0f;
            }
            const float ww = w[base + i];
            ar = fmaf(ww, rgb[3 * (base + i) + 0], ar);
            ag = fmaf(ww, rgb[3 * (base + i) + 1], ag);
            ab = fmaf(ww, rgb[3 * (base + i) + 2], ab);
        }
    } else {
        key = -1 - lane;   // unique sentinel: never merges, value is zero
    }

    // Segmented suffix reduction across the warp (keys sorted => runs are
    // lane-contiguous; after 5 steps each run-head holds the run total).
    const unsigned full = 0xffffffffu;
#pragma unroll
    for (int off = 1; off < 32; off <<= 1) {
        const int   nk = __shfl_down_sync(full, key, off);
        const float nr = __shfl_down_sync(full, ar, off);
        const float ng = __shfl_down_sync(full, ag, off);
        const float nb = __shfl_down_sync(full, ab, off);
        if (lane + off < 32 && nk == key) {
            ar += nr; ag += ng; ab += nb;
        }
    }

    const int pk = __shfl_up_sync(full, key, 1);
    const bool head = (lane == 0) || (pk != key);
    if (head && valid) {
        atomicAdd(out + 3 * key + 0, ar);
        atomicAdd(out + 3 * key + 1, ag);
        atomicAdd(out + 3 * key + 2, ab);
    }
}

extern "C" void kernel_launch(void* const* d_in, const int* in_sizes, int n_in,
                              void* d_out, int out_size) {
    const int*   seg = (const int*)d_in[0];
    const float* rgb = (const float*)d_in[1];
    const float* w   = (const float*)d_in[2];
    float*       out = (float*)d_out;
    const int n = in_sizes[0];

    // Zero the (poisoned) output. Graph-capturable memset node; same-stream
    // ordering completes it before the atomics.
    if (out_size > 0)
        cudaMemsetAsync(out, 0, (size_t)out_size * sizeof(float));

    const long long nwarps  = ((long long)n + 127) / 128;
    const long long nthread = nwarps * 32;
    const int nblocks = (int)((nthread + 255) / 256);
    integrate_kernel<<<nblocks, 256>>>(seg, rgb, w, out, n);
}

// round 17
// speedup vs baseline: 1.0185x; 1.0185x over previous
#include <cuda_runtime.h>

// Sorted segment-sum: pred_rgb[r] = sum over samples s of ray r of w_s * rgb_s
// CONVERGED FINAL (6 reproductions: 29.15/29.4/29.47/29.98/30.1/30.4us;
// kernel 27.5-29.2us at 5.9-6.3TB/s = B300 path-independent LTS cap
// ~6300 B/cyc; variance = NAT-clock DVFS).
// Controlled experiments falsified all structural alternatives:
//   R5 smem-staged rgb (L1 pipe contention), R6 256-sample tiles (occ loss),
//   R8 persistent (reg bloat 46), R9/R10 persistent iso-occupancy (grid-
//   stride loop serializes load batches vs 65K independent warps),
//   R14 block 512 (neutral, worse occ quantization).
// Configuration:
//  - flat launch, warp tile = 128 samples, lane chunk = 4: seg int4 +
//    w float4 coalesced, rgb 3x float4 at 48B lane stride, all __ldcs
//    (169MB read-once > 126MB L2, evict-first).
//  - per-lane register accumulation; rare internal segment boundary flushes
//    directly with atomicAdd (RED, no return).
//  - warp segmented suffix reduction over tail partials (sorted keys => runs
//    are lane-contiguous; 5 shfl.down steps); only run-head lanes emit the
//    3 atomics (~9 RED / 128 samples => ~600K total vs 25M naive).
//  - cudaMemsetAsync graph memset node zeroes the poisoned output; same-
//    stream ordering completes it before any atomics (semantically required).

__global__ void __launch_bounds__(256) integrate_kernel(
    const int*   __restrict__ seg,
    const float* __restrict__ rgb,
    const float* __restrict__ w,
    float*       __restrict__ out,
    int n)
{
    const int lane = threadIdx.x & 31;
    const long long warp_global =
        ((long long)blockIdx.x * blockDim.x + threadIdx.x) >> 5;
    const long long tileBase = warp_global * 128;
    if (tileBase >= n) return;            // warp-uniform exit only

    const long long base = tileBase + 4LL * lane;
    const bool valid = base < n;

    int   key;
    float ar = 0.0f, ag = 0.0f, ab = 0.0f;

    if (valid && base + 4 <= n) {
        // Front-batched streaming loads (evict-first).
        const int4   s4 = __ldcs(reinterpret_cast<const int4*>(seg + base));
        const float4 w4 = __ldcs(reinterpret_cast<const float4*>(w + base));
        const float4* r4 = reinterpret_cast<const float4*>(rgb + base * 3);
        const float4 ra = __ldcs(r4 + 0);
        const float4 rb = __ldcs(r4 + 1);
        const float4 rc = __ldcs(r4 + 2);

        // AoS float3 layout within the 3 float4s:
        //   s0: ra.x ra.y ra.z | s1: ra.w rb.x rb.y
        //   s2: rb.z rb.w rc.x | s3: rc.y rc.z rc.w
        const int   s[4] = {s4.x, s4.y, s4.z, s4.w};
        const float W[4] = {w4.x, w4.y, w4.z, w4.w};
        const float R[4] = {ra.x, ra.w, rb.z, rc.y};
        const float G[4] = {ra.y, rb.x, rb.w, rc.z};
        const float B[4] = {ra.z, rb.y, rc.x, rc.w};

        key = s[0];
#pragma unroll
        for (int i = 0; i < 4; i++) {
            if (s[i] != key) {                 // rare internal boundary
                atomicAdd(out + 3 * key + 0, ar);
                atomicAdd(out + 3 * key + 1, ag);
                atomicAdd(out + 3 * key + 2, ab);
                key = s[i];
                ar = ag = ab = 0.0f;
            }
            ar = fmaf(W[i], R[i], ar);
            ag = fmaf(W[i], G[i], ag);
            ab = fmaf(W[i], B[i], ab);
        }
    } else if (valid) {
        // Scalar tail path.
        key = seg[base];
        for (int i = 0; i < 4 && base + i < n; i++) {
            const int si = seg[base + i];
            if (si != key) {
                atomicAdd(out + 3 * key + 0, ar);
                atomicAdd(out + 3 * key + 1, ag);
                atomicAdd(out + 3 * key + 2, ab);
                key = si;
                ar = ag = ab = 0.0f;
            }
            const float ww = w[base + i];
            ar = fmaf(ww, rgb[3 * (base + i) + 0], ar);
            ag = fmaf(ww, rgb[3 * (base + i) + 1], ag);
            ab = fmaf(ww, rgb[3 * (base + i) + 2], ab);
        }
    } else {
        key = -1 - lane;   // unique sentinel: never merges, value is zero
    }

    // Segmented suffix reduction across the warp (keys sorted => runs are
    // lane-contiguous; after 5 steps each run-head holds the run total).
    const unsigned full = 0xffffffffu;
#pragma unroll
    for (int off = 1; off < 32; off <<= 1) {
        const int   nk = __shfl_down_sync(full, key, off);
        const float nr = __shfl_down_sync(full, ar, off);
        const float ng = __shfl_down_sync(full, ag, off);
        const float nb = __shfl_down_sync(full, ab, off);
        if (lane + off < 32 && nk == key) {
            ar += nr; ag += ng; ab += nb;
        }
    }

    const int pk = __shfl_up_sync(full, key, 1);
    const bool head = (lane == 0) || (pk != key);
    if (head && valid) {
        atomicAdd(out + 3 * key + 0, ar);
        atomicAdd(out + 3 * key + 1, ag);
        atomicAdd(out + 3 * key + 2, ab);
    }
}

extern "C" void kernel_launch(void* const* d_in, const int* in_sizes, int n_in,
                              void* d_out, int out_size) {
    const int*   seg = (const int*)d_in[0];
    const float* rgb = (const float*)d_in[1];
    const float* w   = (const float*)d_in[2];
    float*       out = (float*)d_out;
    const int n = in_sizes[0];

    // Zero the (poisoned) output. Graph-capturable memset node; same-stream
    // ordering completes it before the atomics.
    if (out_size > 0)
        cudaMemsetAsync(out, 0, (size_t)out_size * sizeof(float));

    const long long nwarps  = ((long long)n + 127) / 128;
    const long long nthread = nwarps * 32;
    const int nblocks = (int)((nthread + 255) / 256);
    integrate_kernel<<<nblocks, 256>>>(seg, rgb, w, out, n);
}